// round 4
// baseline (speedup 1.0000x reference)
#include <cuda_runtime.h>
#include <math.h>

#define Bn  64
#define Tn  1380
#define XDn 96
#define HDn 192
#define CNn 345

// SCALE = 1/sqrt(96*192)
#define SCALEF 0.007365695637359841f

// Scratch (allocation-free rule: __device__ globals)
__device__ float g_Z[(size_t)Bn * CNn * XDn];   //  8.5 MB
__device__ float g_Y[(size_t)Bn * CNn * HDn];   // 16.9 MB
__device__ float g_L[(size_t)Bn * CNn * Tn];    // 122 MB
__device__ float g_mx[Bn * CNn];
__device__ float g_inv[Bn * CNn];

// ---------------------------------------------------------------------------
// Z[b,c,x] = sum_t W2[c,t] * X[b,t,x]     (M=345, N=96, K=1380 per batch)
// Tile: BM=128, BN=96, BK=16; 256 threads, 8x6 micro-tile
// ---------------------------------------------------------------------------
__global__ __launch_bounds__(256) void z_kernel(const float* __restrict__ X,
                                                const float* __restrict__ W2) {
    int b  = blockIdx.y;
    int c0 = blockIdx.x * 128;
    __shared__ float As[128][16];   // W2[c][t]
    __shared__ float Bs[16][96];    // X[t][x]
    int tid = threadIdx.x, tx = tid & 15, ty = tid >> 4;
    float acc[8][6] = {};
    const float* Xb = X + (size_t)b * Tn * XDn;

    for (int k0 = 0; k0 < Tn; k0 += 16) {
        #pragma unroll
        for (int i = 0; i < 8; i++) {
            int l = tid + 256 * i;
            int r = l >> 4, kk = l & 15;
            int c = c0 + r, t = k0 + kk;
            As[r][kk] = (c < CNn && t < Tn) ? W2[(size_t)c * Tn + t] : 0.f;
        }
        #pragma unroll
        for (int i = 0; i < 6; i++) {
            int l = tid + 256 * i;
            int r = l / 96, x = l % 96;
            int t = k0 + r;
            Bs[r][x] = (t < Tn) ? Xb[(size_t)t * XDn + x] : 0.f;
        }
        __syncthreads();
        #pragma unroll
        for (int k = 0; k < 16; k++) {
            float a[8], bv[6];
            #pragma unroll
            for (int i = 0; i < 8; i++) a[i] = As[ty + 16 * i][k];
            #pragma unroll
            for (int j = 0; j < 6; j++) bv[j] = Bs[k][tx + 16 * j];
            #pragma unroll
            for (int i = 0; i < 8; i++)
                #pragma unroll
                for (int j = 0; j < 6; j++)
                    acc[i][j] = fmaf(a[i], bv[j], acc[i][j]);
        }
        __syncthreads();
    }
    float* Zb = g_Z + (size_t)b * CNn * XDn;
    #pragma unroll
    for (int i = 0; i < 8; i++) {
        int c = c0 + ty + 16 * i;
        if (c < CNn)
            #pragma unroll
            for (int j = 0; j < 6; j++)
                Zb[(size_t)c * XDn + tx + 16 * j] = acc[i][j];
    }
}

// ---------------------------------------------------------------------------
// Y[b,c,h] = SCALE * sum_x Z[b,c,x] * W1[x,h]   (tiny: 0.8 GF)
// Block: 8 c-rows, 192 threads (one per h)
// ---------------------------------------------------------------------------
__global__ __launch_bounds__(192) void y_kernel(const float* __restrict__ W1) {
    int b  = blockIdx.y;
    int c0 = blockIdx.x * 8;
    __shared__ float Zs[8][96];
    const float* Zb = g_Z + (size_t)b * CNn * XDn;
    for (int l = threadIdx.x; l < 8 * 96; l += 192) {
        int r = l / 96, x = l % 96;
        int c = c0 + r;
        Zs[r][x] = (c < CNn) ? Zb[(size_t)c * XDn + x] : 0.f;
    }
    __syncthreads();
    int h = threadIdx.x;
    float acc[8] = {};
    for (int x = 0; x < 96; x++) {
        float w = W1[(size_t)x * HDn + h];
        #pragma unroll
        for (int r = 0; r < 8; r++) acc[r] = fmaf(Zs[r][x], w, acc[r]);
    }
    float* Yb = g_Y + (size_t)b * CNn * HDn;
    #pragma unroll
    for (int r = 0; r < 8; r++) {
        int c = c0 + r;
        if (c < CNn) Yb[(size_t)c * HDn + h] = acc[r] * SCALEF;
    }
}

// ---------------------------------------------------------------------------
// L[b,c,u] = Y[b,c,:] . H[b,u,:]          (M=345, N=1380, K=192 per batch)
// Tile: BM=128, BN=128, BK=16; 256 threads, 8x8 micro-tile
// ---------------------------------------------------------------------------
__global__ __launch_bounds__(256) void l_kernel(const float* __restrict__ H) {
    int b  = blockIdx.z;
    int c0 = blockIdx.y * 128;
    int u0 = blockIdx.x * 128;
    __shared__ float As[128][17];   // Y[c][k]
    __shared__ float Bs[128][17];   // H[u][k]
    int tid = threadIdx.x, tx = tid & 15, ty = tid >> 4;
    float acc[8][8] = {};
    const float* Yb = g_Y + (size_t)b * CNn * HDn;
    const float* Hb = H + (size_t)b * Tn * HDn;

    for (int k0 = 0; k0 < HDn; k0 += 16) {
        #pragma unroll
        for (int i = 0; i < 8; i++) {
            int l = tid + 256 * i;
            int r = l >> 4, kk = l & 15;
            int c = c0 + r;
            As[r][kk] = (c < CNn) ? Yb[(size_t)c * HDn + k0 + kk] : 0.f;
            int u = u0 + r;
            Bs[r][kk] = (u < Tn) ? Hb[(size_t)u * HDn + k0 + kk] : 0.f;
        }
        __syncthreads();
        #pragma unroll
        for (int k = 0; k < 16; k++) {
            float a[8], bv[8];
            #pragma unroll
            for (int i = 0; i < 8; i++) a[i] = As[ty + 16 * i][k];
            #pragma unroll
            for (int j = 0; j < 8; j++) bv[j] = Bs[tx + 16 * j][k];
            #pragma unroll
            for (int i = 0; i < 8; i++)
                #pragma unroll
                for (int j = 0; j < 8; j++)
                    acc[i][j] = fmaf(a[i], bv[j], acc[i][j]);
        }
        __syncthreads();
    }
    float* Lb = g_L + (size_t)b * CNn * Tn;
    #pragma unroll
    for (int i = 0; i < 8; i++) {
        int c = c0 + ty + 16 * i;
        if (c < CNn) {
            #pragma unroll
            for (int j = 0; j < 8; j++) {
                int u = u0 + tx + 16 * j;
                if (u < Tn) Lb[(size_t)c * Tn + u] = acc[i][j];
            }
        }
    }
}

// ---------------------------------------------------------------------------
// Per-row max and 1/sum(exp(L-max)) over u (row length 1380)
// ---------------------------------------------------------------------------
__global__ __launch_bounds__(256) void stat_kernel() {
    int row = blockIdx.x;                       // b*CN + c
    const float* Lr = g_L + (size_t)row * Tn;
    int tid = threadIdx.x;
    __shared__ float red[256];

    float m = -1e30f;
    for (int u = tid; u < Tn; u += 256) m = fmaxf(m, Lr[u]);
    red[tid] = m; __syncthreads();
    for (int s = 128; s > 0; s >>= 1) {
        if (tid < s) red[tid] = fmaxf(red[tid], red[tid + s]);
        __syncthreads();
    }
    m = red[0];
    __syncthreads();

    float sum = 0.f;
    for (int u = tid; u < Tn; u += 256) sum += __expf(Lr[u] - m);
    red[tid] = sum; __syncthreads();
    for (int s = 128; s > 0; s >>= 1) {
        if (tid < s) red[tid] += red[tid + s];
        __syncthreads();
    }
    if (tid == 0) { g_mx[row] = m; g_inv[row] = 1.0f / red[0]; }
}

// ---------------------------------------------------------------------------
// C[b,c,h] = sum_u softmax(L)[b,c,u] * H[b,u,h]  (M=345, N=192, K=1380)
// Softmax applied on-the-fly while loading the P tile.
// Tile: BM=128, BN=64, BK=16; 256 threads, 8x4 micro-tile
// ---------------------------------------------------------------------------
__global__ __launch_bounds__(256) void c_kernel(const float* __restrict__ H,
                                                float* __restrict__ out) {
    int b  = blockIdx.z;
    int c0 = blockIdx.y * 128;
    int h0 = blockIdx.x * 64;
    __shared__ float As[128][17];   // P[c][u-chunk]
    __shared__ float Bs[16][64];    // H[u][h]
    __shared__ float mxs[128], invs[128];
    int tid = threadIdx.x, tx = tid & 15, ty = tid >> 4;

    if (tid < 128) {
        int c = c0 + tid;
        if (c < CNn) {
            mxs[tid]  = g_mx[b * CNn + c];
            invs[tid] = g_inv[b * CNn + c];
        } else {
            mxs[tid] = 0.f; invs[tid] = 0.f;
        }
    }
    __syncthreads();

    float acc[8][4] = {};
    const float* Lb = g_L + (size_t)b * CNn * Tn;
    const float* Hb = H + (size_t)b * Tn * HDn;

    for (int k0 = 0; k0 < Tn; k0 += 16) {
        #pragma unroll
        for (int i = 0; i < 8; i++) {
            int l = tid + 256 * i;
            int r = l >> 4, kk = l & 15;
            int c = c0 + r, u = k0 + kk;
            As[r][kk] = (c < CNn && u < Tn)
                        ? __expf(Lb[(size_t)c * Tn + u] - mxs[r]) * invs[r]
                        : 0.f;
        }
        #pragma unroll
        for (int i = 0; i < 4; i++) {
            int l = tid + 256 * i;
            int kk = l >> 6, hh = l & 63;
            int u = k0 + kk;
            Bs[kk][hh] = (u < Tn) ? Hb[(size_t)u * HDn + h0 + hh] : 0.f;
        }
        __syncthreads();
        #pragma unroll
        for (int k = 0; k < 16; k++) {
            float a[8], bv[4];
            #pragma unroll
            for (int i = 0; i < 8; i++) a[i] = As[ty + 16 * i][k];
            #pragma unroll
            for (int j = 0; j < 4; j++) bv[j] = Bs[k][tx + 16 * j];
            #pragma unroll
            for (int i = 0; i < 8; i++)
                #pragma unroll
                for (int j = 0; j < 4; j++)
                    acc[i][j] = fmaf(a[i], bv[j], acc[i][j]);
        }
        __syncthreads();
    }
    #pragma unroll
    for (int i = 0; i < 8; i++) {
        int c = c0 + ty + 16 * i;
        if (c < CNn) {
            #pragma unroll
            for (int j = 0; j < 4; j++)
                out[((size_t)b * CNn + c) * HDn + h0 + tx + 16 * j] = acc[i][j];
        }
    }
}

// ---------------------------------------------------------------------------
extern "C" void kernel_launch(void* const* d_in, const int* in_sizes, int n_in,
                              void* d_out, int out_size) {
    const float* X  = (const float*)d_in[0];
    const float* H  = (const float*)d_in[1];
    const float* W1 = (const float*)d_in[2];
    const float* W2 = (const float*)d_in[3];
    float* out = (float*)d_out;

    z_kernel<<<dim3(3, Bn), 256>>>(X, W2);                 // ceil(345/128)=3
    y_kernel<<<dim3(44, Bn), 192>>>(W1);                   // ceil(345/8)=44
    l_kernel<<<dim3(11, 3, Bn), 256>>>(H);                 // ceil(1380/128)=11
    stat_kernel<<<Bn * CNn, 256>>>();
    c_kernel<<<dim3(3, 3, Bn), 256>>>(H, out);             // 192/64=3, ceil(345/128)=3
}

// round 6
// speedup vs baseline: 1.6736x; 1.6736x over previous
#include <cuda_runtime.h>
#include <math.h>

#define Bn  64
#define Tn  1380
#define XDn 96
#define HDn 192
#define CNn 345
#define NUT 11            // ceil(1380/128) u-tiles in l_kernel

// SCALE = 1/sqrt(96*192)
#define SCALEF 0.007365695637359841f
#define NEGBIG -1e30f

// Scratch (allocation-free rule: __device__ globals)
__device__ float g_Z[(size_t)Bn * CNn * XDn];    //  8.5 MB
__device__ float g_Y[(size_t)Bn * CNn * HDn];    // 16.9 MB
__device__ float g_L[(size_t)Bn * CNn * Tn];     // 122 MB
__device__ float g_pm[(size_t)Bn * CNn * NUT];   // per-(row,utile) max
__device__ float g_ps[(size_t)Bn * CNn * NUT];   // per-(row,utile) sumexp
__device__ float g_mx[Bn * CNn];
__device__ float g_inv[Bn * CNn];

// ---------------------------------------------------------------------------
// Z[b,c,x] = sum_t W2[c,t] * X[b,t,x]     (M=345, N=96, K=1380 per batch)
// ---------------------------------------------------------------------------
__global__ __launch_bounds__(256) void z_kernel(const float* __restrict__ X,
                                                const float* __restrict__ W2) {
    int b  = blockIdx.y;
    int c0 = blockIdx.x * 128;
    __shared__ float As[128][16];   // W2[c][t]
    __shared__ float Bs[16][96];    // X[t][x]
    int tid = threadIdx.x, tx = tid & 15, ty = tid >> 4;
    float acc[8][6] = {};
    const float* Xb = X + (size_t)b * Tn * XDn;

    for (int k0 = 0; k0 < Tn; k0 += 16) {
        #pragma unroll
        for (int i = 0; i < 8; i++) {
            int l = tid + 256 * i;
            int r = l >> 4, kk = l & 15;
            int c = c0 + r, t = k0 + kk;
            As[r][kk] = (c < CNn && t < Tn) ? W2[(size_t)c * Tn + t] : 0.f;
        }
        #pragma unroll
        for (int i = 0; i < 6; i++) {
            int l = tid + 256 * i;
            int r = l / 96, x = l % 96;
            int t = k0 + r;
            Bs[r][x] = (t < Tn) ? Xb[(size_t)t * XDn + x] : 0.f;
        }
        __syncthreads();
        #pragma unroll
        for (int k = 0; k < 16; k++) {
            float a[8], bv[6];
            #pragma unroll
            for (int i = 0; i < 8; i++) a[i] = As[ty + 16 * i][k];
            #pragma unroll
            for (int j = 0; j < 6; j++) bv[j] = Bs[k][tx + 16 * j];
            #pragma unroll
            for (int i = 0; i < 8; i++)
                #pragma unroll
                for (int j = 0; j < 6; j++)
                    acc[i][j] = fmaf(a[i], bv[j], acc[i][j]);
        }
        __syncthreads();
    }
    float* Zb = g_Z + (size_t)b * CNn * XDn;
    #pragma unroll
    for (int i = 0; i < 8; i++) {
        int c = c0 + ty + 16 * i;
        if (c < CNn)
            #pragma unroll
            for (int j = 0; j < 6; j++)
                Zb[(size_t)c * XDn + tx + 16 * j] = acc[i][j];
    }
}

// ---------------------------------------------------------------------------
// Y[b,c,h] = SCALE * sum_x Z[b,c,x] * W1[x,h]
// ---------------------------------------------------------------------------
__global__ __launch_bounds__(192) void y_kernel(const float* __restrict__ W1) {
    int b  = blockIdx.y;
    int c0 = blockIdx.x * 8;
    __shared__ float Zs[8][96];
    const float* Zb = g_Z + (size_t)b * CNn * XDn;
    for (int l = threadIdx.x; l < 8 * 96; l += 192) {
        int r = l / 96, x = l % 96;
        int c = c0 + r;
        Zs[r][x] = (c < CNn) ? Zb[(size_t)c * XDn + x] : 0.f;
    }
    __syncthreads();
    int h = threadIdx.x;
    float acc[8] = {};
    for (int x = 0; x < 96; x++) {
        float w = W1[(size_t)x * HDn + h];
        #pragma unroll
        for (int r = 0; r < 8; r++) acc[r] = fmaf(Zs[r][x], w, acc[r]);
    }
    float* Yb = g_Y + (size_t)b * CNn * HDn;
    #pragma unroll
    for (int r = 0; r < 8; r++) {
        int c = c0 + r;
        if (c < CNn) Yb[(size_t)c * HDn + h] = acc[r] * SCALEF;
    }
}

// ---------------------------------------------------------------------------
// L[b,c,u] = Y[b,c,:] . H[b,u,:]  (M=345, N=1380, K=192)
// k-major smem, float4 fragments, prefetch, fused per-(row,utile) softmax
// partials (max, sumexp) reduced across the 16 tx lanes via shfl_xor.
// Tile: BM=128, BN=128, BK=16; 256 threads, 8x8 micro.
// ---------------------------------------------------------------------------
__global__ __launch_bounds__(256) void l_kernel(const float* __restrict__ H) {
    int b  = blockIdx.z;
    int c0 = blockIdx.y * 128;
    int u0 = blockIdx.x * 128;
    int ut = blockIdx.x;
    __shared__ float As[16][132];   // [k][c]
    __shared__ float Bs[16][132];   // [k][u]
    int tid = threadIdx.x, tx = tid & 15, ty = tid >> 4;

    const float* Yb = g_Y + (size_t)b * CNn * HDn;
    const float* Hb = H + (size_t)b * Tn * HDn;

    // fill mapping: each thread owns one (c,u) row pair, 8 consecutive k
    int rf  = tid >> 1;            // 0..127
    int k4  = (tid & 1) * 8;       // 0 or 8
    int ca  = c0 + rf;
    int ua  = u0 + rf;
    bool cav = ca < CNn, uav = ua < Tn;
    const float* Yp = Yb + (size_t)(cav ? ca : 0) * HDn + k4;
    const float* Hp = Hb + (size_t)(uav ? ua : 0) * HDn + k4;

    float4 ya0, ya1, ha0, ha1;
    const float4 z4 = make_float4(0.f, 0.f, 0.f, 0.f);
    ya0 = cav ? *(const float4*)(Yp + 0) : z4;
    ya1 = cav ? *(const float4*)(Yp + 4) : z4;
    ha0 = uav ? *(const float4*)(Hp + 0) : z4;
    ha1 = uav ? *(const float4*)(Hp + 4) : z4;

    float acc[8][8] = {};

    for (int k0 = 0; k0 < HDn; k0 += 16) {
        As[k4 + 0][rf] = ya0.x; As[k4 + 1][rf] = ya0.y;
        As[k4 + 2][rf] = ya0.z; As[k4 + 3][rf] = ya0.w;
        As[k4 + 4][rf] = ya1.x; As[k4 + 5][rf] = ya1.y;
        As[k4 + 6][rf] = ya1.z; As[k4 + 7][rf] = ya1.w;
        Bs[k4 + 0][rf] = ha0.x; Bs[k4 + 1][rf] = ha0.y;
        Bs[k4 + 2][rf] = ha0.z; Bs[k4 + 3][rf] = ha0.w;
        Bs[k4 + 4][rf] = ha1.x; Bs[k4 + 5][rf] = ha1.y;
        Bs[k4 + 6][rf] = ha1.z; Bs[k4 + 7][rf] = ha1.w;
        __syncthreads();
        if (k0 + 16 < HDn) {
            ya0 = cav ? *(const float4*)(Yp + k0 + 16) : z4;
            ya1 = cav ? *(const float4*)(Yp + k0 + 20) : z4;
            ha0 = uav ? *(const float4*)(Hp + k0 + 16) : z4;
            ha1 = uav ? *(const float4*)(Hp + k0 + 20) : z4;
        }
        #pragma unroll
        for (int k = 0; k < 16; k++) {
            float4 a0 = *(const float4*)&As[k][ty * 4];
            float4 a1 = *(const float4*)&As[k][64 + ty * 4];
            float4 b0 = *(const float4*)&Bs[k][tx * 4];
            float4 b1 = *(const float4*)&Bs[k][64 + tx * 4];
            float av[8] = {a0.x, a0.y, a0.z, a0.w, a1.x, a1.y, a1.z, a1.w};
            float bv[8] = {b0.x, b0.y, b0.z, b0.w, b1.x, b1.y, b1.z, b1.w};
            #pragma unroll
            for (int i = 0; i < 8; i++)
                #pragma unroll
                for (int j = 0; j < 8; j++)
                    acc[i][j] = fmaf(av[i], bv[j], acc[i][j]);
        }
        __syncthreads();
    }

    float* Lb = g_L + (size_t)b * CNn * Tn;
    int u_lo = u0 + tx * 4;
    int u_hi = u0 + 64 + tx * 4;

    #pragma unroll
    for (int i = 0; i < 8; i++) {
        int c = c0 + ((i < 4) ? (ty * 4 + i) : (64 + ty * 4 + i - 4));
        // per-row tile max (mask invalid u)
        float m = NEGBIG;
        #pragma unroll
        for (int j = 0; j < 8; j++) {
            int u = (j < 4) ? (u_lo + j) : (u_hi + j - 4);
            if (u < Tn) m = fmaxf(m, acc[i][j]);
        }
        #pragma unroll
        for (int off = 1; off < 16; off <<= 1)
            m = fmaxf(m, __shfl_xor_sync(0xffffffffu, m, off));
        float s = 0.f;
        #pragma unroll
        for (int j = 0; j < 8; j++) {
            int u = (j < 4) ? (u_lo + j) : (u_hi + j - 4);
            if (u < Tn) s += __expf(acc[i][j] - m);
        }
        #pragma unroll
        for (int off = 1; off < 16; off <<= 1)
            s += __shfl_xor_sync(0xffffffffu, s, off);

        if (c < CNn) {
            if (tx == 0) {
                size_t ridx = ((size_t)b * CNn + c) * NUT + ut;
                g_pm[ridx] = m;
                g_ps[ridx] = s;
            }
            float4 v0 = make_float4(acc[i][0], acc[i][1], acc[i][2], acc[i][3]);
            *(float4*)&Lb[(size_t)c * Tn + u_lo] = v0;
            if (u_hi + 3 < Tn) {
                float4 v1 = make_float4(acc[i][4], acc[i][5], acc[i][6], acc[i][7]);
                *(float4*)&Lb[(size_t)c * Tn + u_hi] = v1;
            }
        }
    }
}

// ---------------------------------------------------------------------------
// Combine per-tile softmax partials: M = max m_t; inv = 1/sum s_t*exp(m_t-M)
// ---------------------------------------------------------------------------
__global__ __launch_bounds__(256) void combine_kernel() {
    int idx = blockIdx.x * 256 + threadIdx.x;
    if (idx >= Bn * CNn) return;
    const float* pm = g_pm + (size_t)idx * NUT;
    const float* ps = g_ps + (size_t)idx * NUT;
    float m = NEGBIG;
    #pragma unroll
    for (int t = 0; t < NUT; t++) m = fmaxf(m, pm[t]);
    float s = 0.f;
    #pragma unroll
    for (int t = 0; t < NUT; t++) s += ps[t] * __expf(pm[t] - m);
    g_mx[idx]  = m;
    g_inv[idx] = 1.0f / s;
}

// ---------------------------------------------------------------------------
// C[b,c,h] = sum_u softmax(L)[b,c,u] * H[b,u,h]  (M=345, N=192 full, K=1380)
// L read ONCE, exp applied once during smem fill. k-major smem, float4,
// prefetch. Tile: BM=64, BN=192, BK=16; 256 threads, 4x12 micro.
// ---------------------------------------------------------------------------
__global__ __launch_bounds__(256) void c_kernel(const float* __restrict__ H,
                                                float* __restrict__ out) {
    int b  = blockIdx.y;
    int c0 = blockIdx.x * 64;
    __shared__ float As[16][68];    // [u'][c] = P
    __shared__ float Bs[16][196];   // [u'][h]
    __shared__ float mxs[64], invs[64];
    int tid = threadIdx.x, tx = tid & 15, ty = tid >> 4;

    if (tid < 64) {
        int c = c0 + tid;
        if (c < CNn) {
            mxs[tid]  = g_mx[b * CNn + c];
            invs[tid] = g_inv[b * CNn + c];
        } else { mxs[tid] = 0.f; invs[tid] = 0.f; }
    }
    __syncthreads();

    const float* Lb = g_L + (size_t)b * CNn * Tn;
    const float* Hb = H + (size_t)b * Tn * HDn;

    // fill mapping
    int cc = tid >> 2;              // 0..63 (c row)
    int j4 = (tid & 3) * 4;         // u' chunk for A fill
    int rr = ty;                    // u' row for B fill (0..15)
    bool cv = (c0 + cc) < CNn;
    const float* Lp = Lb + (size_t)(cv ? (c0 + cc) : 0) * Tn + j4;
    const float* Hp = Hb + (size_t)rr * HDn + tx * 4;
    float mxc = mxs[cc], invc = invs[cc];

    const float4 z4 = make_float4(0.f, 0.f, 0.f, 0.f);
    const float4 n4 = make_float4(NEGBIG, NEGBIG, NEGBIG, NEGBIG);

    float4 la, hb0, hb1, hb2;
    la  = (cv && (0 + j4) < Tn) ? *(const float4*)(Lp) : n4;
    hb0 = (rr < Tn) ? *(const float4*)(Hp + 0)   : z4;
    hb1 = (rr < Tn) ? *(const float4*)(Hp + 64)  : z4;
    hb2 = (rr < Tn) ? *(const float4*)(Hp + 128) : z4;

    float acc[4][12] = {};

    for (int u0 = 0; u0 < Tn; u0 += 16) {
        As[j4 + 0][cc] = __expf(la.x - mxc) * invc;
        As[j4 + 1][cc] = __expf(la.y - mxc) * invc;
        As[j4 + 2][cc] = __expf(la.z - mxc) * invc;
        As[j4 + 3][cc] = __expf(la.w - mxc) * invc;
        *(float4*)&Bs[rr][tx * 4 + 0]   = hb0;
        *(float4*)&Bs[rr][tx * 4 + 64]  = hb1;
        *(float4*)&Bs[rr][tx * 4 + 128] = hb2;
        __syncthreads();

        int un = u0 + 16;
        if (un < Tn) {
            la = (cv && (un + j4) < Tn) ? *(const float4*)(Lp + un) : n4;
            bool uv = (un + rr) < Tn;
            const float* hp = Hp + (size_t)un * HDn;
            hb0 = uv ? *(const float4*)(hp + 0)   : z4;
            hb1 = uv ? *(const float4*)(hp + 64)  : z4;
            hb2 = uv ? *(const float4*)(hp + 128) : z4;
        }

        #pragma unroll
        for (int k = 0; k < 16; k++) {
            float4 a  = *(const float4*)&As[k][ty * 4];
            float4 b0 = *(const float4*)&Bs[k][tx * 4];
            float4 b1 = *(const float4*)&Bs[k][tx * 4 + 64];
            float4 b2 = *(const float4*)&Bs[k][tx * 4 + 128];
            float av[4]  = {a.x, a.y, a.z, a.w};
            float bv[12] = {b0.x, b0.y, b0.z, b0.w,
                            b1.x, b1.y, b1.z, b1.w,
                            b2.x, b2.y, b2.z, b2.w};
            #pragma unroll
            for (int i = 0; i < 4; i++)
                #pragma unroll
                for (int j = 0; j < 12; j++)
                    acc[i][j] = fmaf(av[i], bv[j], acc[i][j]);
        }
        __syncthreads();
    }

    #pragma unroll
    for (int i = 0; i < 4; i++) {
        int c = c0 + ty * 4 + i;
        if (c < CNn) {
            float* op = out + ((size_t)b * CNn + c) * HDn;
            #pragma unroll
            for (int q = 0; q < 3; q++) {
                float4 v = make_float4(acc[i][q * 4 + 0], acc[i][q * 4 + 1],
                                       acc[i][q * 4 + 2], acc[i][q * 4 + 3]);
                *(float4*)&op[tx * 4 + 64 * q] = v;
            }
        }
    }
}

// ---------------------------------------------------------------------------
extern "C" void kernel_launch(void* const* d_in, const int* in_sizes, int n_in,
                              void* d_out, int out_size) {
    const float* X  = (const float*)d_in[0];
    const float* H  = (const float*)d_in[1];
    const float* W1 = (const float*)d_in[2];
    const float* W2 = (const float*)d_in[3];
    float* out = (float*)d_out;

    z_kernel<<<dim3(3, Bn), 256>>>(X, W2);
    y_kernel<<<dim3(44, Bn), 192>>>(W1);
    l_kernel<<<dim3(NUT, 3, Bn), 256>>>(H);
    combine_kernel<<<(Bn * CNn + 255) / 256, 256>>>();
    c_kernel<<<dim3(6, Bn), 256>>>(H, out);
}

// round 8
// speedup vs baseline: 2.0572x; 1.2292x over previous
#include <cuda_runtime.h>
#include <math.h>

#define Bn  64
#define Tn  1380
#define XDn 96
#define HDn 192
#define CNn 345
#define NUT 11            // ceil(1380/128) u-tiles in l_kernel

// SCALE = 1/sqrt(96*192)
#define SCALEF 0.007365695637359841f
#define NEGBIG -1e30f

typedef unsigned long long u64;

// ---- packed fp32x2 helpers (Blackwell FFMA2; exact fp32 per lane) ----------
__device__ __forceinline__ u64 pack2(float x, float y) {
    u64 r; asm("mov.b64 %0, {%1, %2};" : "=l"(r) : "f"(x), "f"(y)); return r;
}
__device__ __forceinline__ float2 unpack2(u64 v) {
    float lo, hi; asm("mov.b64 {%0, %1}, %2;" : "=f"(lo), "=f"(hi) : "l"(v));
    return make_float2(lo, hi);
}
__device__ __forceinline__ void fma2(u64& d, u64 a, u64 b) {
    asm("fma.rn.f32x2 %0, %1, %2, %0;" : "+l"(d) : "l"(a), "l"(b));
}

// Scratch (allocation-free rule: __device__ globals)
__device__ float g_Z[(size_t)Bn * CNn * XDn];    //  8.5 MB
__device__ float g_Y[(size_t)Bn * CNn * HDn];    // 16.9 MB
__device__ float g_L[(size_t)Bn * CNn * Tn];     // 122 MB
__device__ float g_pm[(size_t)Bn * CNn * NUT];   // per-(row,utile) max
__device__ float g_ps[(size_t)Bn * CNn * NUT];   // per-(row,utile) sumexp
__device__ float g_mx[Bn * CNn];
__device__ float g_inv[Bn * CNn];

// guarded float4 row load (for Tn-tail, 1380 % 16 != 0)
__device__ __forceinline__ float4 ld4g(const float* row, int t, bool ok) {
    float4 v = make_float4(0.f, 0.f, 0.f, 0.f);
    if (ok) {
        if (t + 3 < Tn) v = *(const float4*)(row + t);
        else {
            if (t     < Tn) v.x = row[t];
            if (t + 1 < Tn) v.y = row[t + 1];
            if (t + 2 < Tn) v.z = row[t + 2];
            if (t + 3 < Tn) v.w = row[t + 3];
        }
    }
    return v;
}

// ---------------------------------------------------------------------------
// Z[b,c,x] = sum_t W2[c,t] * X[b,t,x]   (M=345, N=96, K=1380)
// k-major smem, FFMA2 inner loop. BM=128, BN=96, BK=16; 256 thr, 8x6 micro.
// ---------------------------------------------------------------------------
__global__ __launch_bounds__(256) void z_kernel(const float* __restrict__ X,
                                                const float* __restrict__ W2) {
    int b  = blockIdx.y;
    int c0 = blockIdx.x * 128;
    __shared__ float As[16][132];   // [t'][c]
    __shared__ float Bs[16][100];   // [t'][x]
    int tid = threadIdx.x, tx = tid & 15, ty = tid >> 4;
    const float* Xb = X + (size_t)b * Tn * XDn;

    // A fill mapping: thread -> (c-row rf, t-chunk k4)
    int rf = tid >> 1;
    int k4 = (tid & 1) * 8;
    int ca = c0 + rf;
    bool cav = ca < CNn;
    const float* W2r = W2 + (size_t)(cav ? ca : 0) * Tn;

    // B fill mapping: 3 float2 per thread over 16x96
    int brow[3], bx2[3];
    #pragma unroll
    for (int i = 0; i < 3; i++) {
        int l = tid + 256 * i;
        brow[i] = l / 48;
        bx2[i]  = (l % 48) * 2;
    }

    float4 wa0 = ld4g(W2r, k4,     cav);
    float4 wa1 = ld4g(W2r, k4 + 4, cav);
    float2 xb[3];
    #pragma unroll
    for (int i = 0; i < 3; i++) {
        int t = brow[i];
        xb[i] = (t < Tn) ? *(const float2*)(Xb + (size_t)t * XDn + bx2[i])
                         : make_float2(0.f, 0.f);
    }

    u64 acc2[8][3] = {};

    for (int k0 = 0; k0 < Tn; k0 += 16) {
        As[k4 + 0][rf] = wa0.x; As[k4 + 1][rf] = wa0.y;
        As[k4 + 2][rf] = wa0.z; As[k4 + 3][rf] = wa0.w;
        As[k4 + 4][rf] = wa1.x; As[k4 + 5][rf] = wa1.y;
        As[k4 + 6][rf] = wa1.z; As[k4 + 7][rf] = wa1.w;
        #pragma unroll
        for (int i = 0; i < 3; i++)
            *(float2*)&Bs[brow[i]][bx2[i]] = xb[i];
        __syncthreads();

        if (k0 + 16 < Tn) {
            wa0 = ld4g(W2r, k0 + 16 + k4,     cav);
            wa1 = ld4g(W2r, k0 + 16 + k4 + 4, cav);
            #pragma unroll
            for (int i = 0; i < 3; i++) {
                int t = k0 + 16 + brow[i];
                xb[i] = (t < Tn) ? *(const float2*)(Xb + (size_t)t * XDn + bx2[i])
                                 : make_float2(0.f, 0.f);
            }
        }

        #pragma unroll
        for (int k = 0; k < 16; k++) {
            float4 a0 = *(const float4*)&As[k][ty * 4];
            float4 a1 = *(const float4*)&As[k][64 + ty * 4];
            u64 bp[3];
            bp[0] = *(const u64*)&Bs[k][tx * 6 + 0];
            bp[1] = *(const u64*)&Bs[k][tx * 6 + 2];
            bp[2] = *(const u64*)&Bs[k][tx * 6 + 4];
            float av[8] = {a0.x, a0.y, a0.z, a0.w, a1.x, a1.y, a1.z, a1.w};
            u64 ap[8];
            #pragma unroll
            for (int i = 0; i < 8; i++) ap[i] = pack2(av[i], av[i]);
            #pragma unroll
            for (int i = 0; i < 8; i++)
                #pragma unroll
                for (int j = 0; j < 3; j++)
                    fma2(acc2[i][j], ap[i], bp[j]);
        }
        __syncthreads();
    }

    float* Zb = g_Z + (size_t)b * CNn * XDn;
    #pragma unroll
    for (int i = 0; i < 8; i++) {
        int c = c0 + ((i < 4) ? (ty * 4 + i) : (64 + ty * 4 + i - 4));
        if (c < CNn) {
            float* zp = Zb + (size_t)c * XDn + tx * 6;
            #pragma unroll
            for (int j = 0; j < 3; j++) {
                float2 f = unpack2(acc2[i][j]);
                *(float2*)(zp + 2 * j) = f;
            }
        }
    }
}

// ---------------------------------------------------------------------------
// Y[b,c,h] = SCALE * sum_x Z[b,c,x] * W1[x,h]
// ---------------------------------------------------------------------------
__global__ __launch_bounds__(192) void y_kernel(const float* __restrict__ W1) {
    int b  = blockIdx.y;
    int c0 = blockIdx.x * 8;
    __shared__ float Zs[8][96];
    const float* Zb = g_Z + (size_t)b * CNn * XDn;
    for (int l = threadIdx.x; l < 8 * 96; l += 192) {
        int r = l / 96, x = l % 96;
        int c = c0 + r;
        Zs[r][x] = (c < CNn) ? Zb[(size_t)c * XDn + x] : 0.f;
    }
    __syncthreads();
    int h = threadIdx.x;
    float acc[8] = {};
    for (int x = 0; x < 96; x++) {
        float w = W1[(size_t)x * HDn + h];
        #pragma unroll
        for (int r = 0; r < 8; r++) acc[r] = fmaf(Zs[r][x], w, acc[r]);
    }
    float* Yb = g_Y + (size_t)b * CNn * HDn;
    #pragma unroll
    for (int r = 0; r < 8; r++) {
        int c = c0 + r;
        if (c < CNn) Yb[(size_t)c * HDn + h] = acc[r] * SCALEF;
    }
}

// ---------------------------------------------------------------------------
// L[b,c,u] = Y[b,c,:] . H[b,u,:]  (M=345, N=1380, K=192)
// FFMA2 inner loop; fused per-(row,utile) softmax partials.
// Tile: BM=128, BN=128, BK=16; 256 threads, 8x8 micro.
// ---------------------------------------------------------------------------
__global__ __launch_bounds__(256) void l_kernel(const float* __restrict__ H) {
    int b  = blockIdx.z;
    int c0 = blockIdx.y * 128;
    int u0 = blockIdx.x * 128;
    int ut = blockIdx.x;
    __shared__ float As[16][132];   // [k][c]
    __shared__ float Bs[16][132];   // [k][u]
    int tid = threadIdx.x, tx = tid & 15, ty = tid >> 4;

    const float* Yb = g_Y + (size_t)b * CNn * HDn;
    const float* Hb = H + (size_t)b * Tn * HDn;

    int rf  = tid >> 1;            // 0..127
    int k4  = (tid & 1) * 8;       // 0 or 8
    int ca  = c0 + rf;
    int ua  = u0 + rf;
    bool cav = ca < CNn, uav = ua < Tn;
    const float* Yp = Yb + (size_t)(cav ? ca : 0) * HDn + k4;
    const float* Hp = Hb + (size_t)(uav ? ua : 0) * HDn + k4;

    float4 ya0, ya1, ha0, ha1;
    const float4 z4 = make_float4(0.f, 0.f, 0.f, 0.f);
    ya0 = cav ? *(const float4*)(Yp + 0) : z4;
    ya1 = cav ? *(const float4*)(Yp + 4) : z4;
    ha0 = uav ? *(const float4*)(Hp + 0) : z4;
    ha1 = uav ? *(const float4*)(Hp + 4) : z4;

    u64 acc2[8][4] = {};

    for (int k0 = 0; k0 < HDn; k0 += 16) {
        As[k4 + 0][rf] = ya0.x; As[k4 + 1][rf] = ya0.y;
        As[k4 + 2][rf] = ya0.z; As[k4 + 3][rf] = ya0.w;
        As[k4 + 4][rf] = ya1.x; As[k4 + 5][rf] = ya1.y;
        As[k4 + 6][rf] = ya1.z; As[k4 + 7][rf] = ya1.w;
        Bs[k4 + 0][rf] = ha0.x; Bs[k4 + 1][rf] = ha0.y;
        Bs[k4 + 2][rf] = ha0.z; Bs[k4 + 3][rf] = ha0.w;
        Bs[k4 + 4][rf] = ha1.x; Bs[k4 + 5][rf] = ha1.y;
        Bs[k4 + 6][rf] = ha1.z; Bs[k4 + 7][rf] = ha1.w;
        __syncthreads();
        if (k0 + 16 < HDn) {
            ya0 = cav ? *(const float4*)(Yp + k0 + 16) : z4;
            ya1 = cav ? *(const float4*)(Yp + k0 + 20) : z4;
            ha0 = uav ? *(const float4*)(Hp + k0 + 16) : z4;
            ha1 = uav ? *(const float4*)(Hp + k0 + 20) : z4;
        }
        #pragma unroll
        for (int k = 0; k < 16; k++) {
            float4 a0 = *(const float4*)&As[k][ty * 4];
            float4 a1 = *(const float4*)&As[k][64 + ty * 4];
            ulonglong2 bq0 = *(const ulonglong2*)&Bs[k][tx * 4];
            ulonglong2 bq1 = *(const ulonglong2*)&Bs[k][64 + tx * 4];
            u64 bp[4] = {bq0.x, bq0.y, bq1.x, bq1.y};
            float av[8] = {a0.x, a0.y, a0.z, a0.w, a1.x, a1.y, a1.z, a1.w};
            u64 ap[8];
            #pragma unroll
            for (int i = 0; i < 8; i++) ap[i] = pack2(av[i], av[i]);
            #pragma unroll
            for (int i = 0; i < 8; i++)
                #pragma unroll
                for (int j = 0; j < 4; j++)
                    fma2(acc2[i][j], ap[i], bp[j]);
        }
        __syncthreads();
    }

    float* Lb = g_L + (size_t)b * CNn * Tn;
    int u_lo = u0 + tx * 4;
    int u_hi = u0 + 64 + tx * 4;

    #pragma unroll
    for (int i = 0; i < 8; i++) {
        int c = c0 + ((i < 4) ? (ty * 4 + i) : (64 + ty * 4 + i - 4));
        float ar[8];
        #pragma unroll
        for (int p = 0; p < 4; p++) {
            float2 f = unpack2(acc2[i][p]);
            ar[2 * p] = f.x; ar[2 * p + 1] = f.y;
        }
        float m = NEGBIG;
        #pragma unroll
        for (int j = 0; j < 8; j++) {
            int u = (j < 4) ? (u_lo + j) : (u_hi + j - 4);
            if (u < Tn) m = fmaxf(m, ar[j]);
        }
        #pragma unroll
        for (int off = 1; off < 16; off <<= 1)
            m = fmaxf(m, __shfl_xor_sync(0xffffffffu, m, off));
        float s = 0.f;
        #pragma unroll
        for (int j = 0; j < 8; j++) {
            int u = (j < 4) ? (u_lo + j) : (u_hi + j - 4);
            if (u < Tn) s += __expf(ar[j] - m);
        }
        #pragma unroll
        for (int off = 1; off < 16; off <<= 1)
            s += __shfl_xor_sync(0xffffffffu, s, off);

        if (c < CNn) {
            if (tx == 0) {
                size_t ridx = ((size_t)b * CNn + c) * NUT + ut;
                g_pm[ridx] = m;
                g_ps[ridx] = s;
            }
            float4 v0 = make_float4(ar[0], ar[1], ar[2], ar[3]);
            *(float4*)&Lb[(size_t)c * Tn + u_lo] = v0;
            if (u_hi + 3 < Tn) {
                float4 v1 = make_float4(ar[4], ar[5], ar[6], ar[7]);
                *(float4*)&Lb[(size_t)c * Tn + u_hi] = v1;
            }
        }
    }
}

// ---------------------------------------------------------------------------
// Combine per-tile softmax partials: M = max m_t; inv = 1/sum s_t*exp(m_t-M)
// ---------------------------------------------------------------------------
__global__ __launch_bounds__(256) void combine_kernel() {
    int idx = blockIdx.x * 256 + threadIdx.x;
    if (idx >= Bn * CNn) return;
    const float* pm = g_pm + (size_t)idx * NUT;
    const float* ps = g_ps + (size_t)idx * NUT;
    float m = NEGBIG;
    #pragma unroll
    for (int t = 0; t < NUT; t++) m = fmaxf(m, pm[t]);
    float s = 0.f;
    #pragma unroll
    for (int t = 0; t < NUT; t++) s += ps[t] * __expf(pm[t] - m);
    g_mx[idx]  = m;
    g_inv[idx] = 1.0f / s;
}

// ---------------------------------------------------------------------------
// C[b,c,h] = sum_u softmax(L)[b,c,u] * H[b,u,h]  (M=345, N=192 full, K=1380)
// L read once, exp once; FFMA2 inner loop.
// Tile: BM=64, BN=192, BK=16; 256 threads, 4x12 micro.
// ---------------------------------------------------------------------------
__global__ __launch_bounds__(256) void c_kernel(const float* __restrict__ H,
                                                float* __restrict__ out) {
    int b  = blockIdx.y;
    int c0 = blockIdx.x * 64;
    __shared__ float As[16][68];    // [u'][c] = P
    __shared__ float Bs[16][196];   // [u'][h]
    __shared__ float mxs[64], invs[64];
    int tid = threadIdx.x, tx = tid & 15, ty = tid >> 4;

    if (tid < 64) {
        int c = c0 + tid;
        if (c < CNn) {
            mxs[tid]  = g_mx[b * CNn + c];
            invs[tid] = g_inv[b * CNn + c];
        } else { mxs[tid] = 0.f; invs[tid] = 0.f; }
    }
    __syncthreads();

    const float* Lb = g_L + (size_t)b * CNn * Tn;
    const float* Hb = H + (size_t)b * Tn * HDn;

    int cc = tid >> 2;              // 0..63 (c row)
    int j4 = (tid & 3) * 4;         // u' chunk for A fill
    int rr = ty;                    // u' row for B fill (0..15)
    bool cv = (c0 + cc) < CNn;
    const float* Lp = Lb + (size_t)(cv ? (c0 + cc) : 0) * Tn + j4;
    const float* Hp = Hb + (size_t)rr * HDn + tx * 4;
    float mxc = mxs[cc], invc = invs[cc];

    const float4 z4 = make_float4(0.f, 0.f, 0.f, 0.f);
    const float4 n4 = make_float4(NEGBIG, NEGBIG, NEGBIG, NEGBIG);

    float4 la, hb0, hb1, hb2;
    la  = (cv && j4 < Tn) ? *(const float4*)(Lp) : n4;
    hb0 = (rr < Tn) ? *(const float4*)(Hp + 0)   : z4;
    hb1 = (rr < Tn) ? *(const float4*)(Hp + 64)  : z4;
    hb2 = (rr < Tn) ? *(const float4*)(Hp + 128) : z4;

    u64 acc2[4][6] = {};

    for (int u0 = 0; u0 < Tn; u0 += 16) {
        As[j4 + 0][cc] = __expf(la.x - mxc) * invc;
        As[j4 + 1][cc] = __expf(la.y - mxc) * invc;
        As[j4 + 2][cc] = __expf(la.z - mxc) * invc;
        As[j4 + 3][cc] = __expf(la.w - mxc) * invc;
        *(float4*)&Bs[rr][tx * 4 + 0]   = hb0;
        *(float4*)&Bs[rr][tx * 4 + 64]  = hb1;
        *(float4*)&Bs[rr][tx * 4 + 128] = hb2;
        __syncthreads();

        int un = u0 + 16;
        if (un < Tn) {
            la = (cv && (un + j4) < Tn) ? *(const float4*)(Lp + un) : n4;
            bool uv = (un + rr) < Tn;
            const float* hp = Hp + (size_t)un * HDn;
            hb0 = uv ? *(const float4*)(hp + 0)   : z4;
            hb1 = uv ? *(const float4*)(hp + 64)  : z4;
            hb2 = uv ? *(const float4*)(hp + 128) : z4;
        }

        #pragma unroll
        for (int k = 0; k < 16; k++) {
            float4 a = *(const float4*)&As[k][ty * 4];
            ulonglong2 bq0 = *(const ulonglong2*)&Bs[k][tx * 4];
            ulonglong2 bq1 = *(const ulonglong2*)&Bs[k][tx * 4 + 64];
            ulonglong2 bq2 = *(const ulonglong2*)&Bs[k][tx * 4 + 128];
            u64 bp[6] = {bq0.x, bq0.y, bq1.x, bq1.y, bq2.x, bq2.y};
            float av[4] = {a.x, a.y, a.z, a.w};
            u64 ap[4];
            #pragma unroll
            for (int i = 0; i < 4; i++) ap[i] = pack2(av[i], av[i]);
            #pragma unroll
            for (int i = 0; i < 4; i++)
                #pragma unroll
                for (int j = 0; j < 6; j++)
                    fma2(acc2[i][j], ap[i], bp[j]);
        }
        __syncthreads();
    }

    #pragma unroll
    for (int i = 0; i < 4; i++) {
        int c = c0 + ty * 4 + i;
        if (c < CNn) {
            float* op = out + ((size_t)b * CNn + c) * HDn;
            #pragma unroll
            for (int q = 0; q < 3; q++) {
                float2 f0 = unpack2(acc2[i][q * 2 + 0]);
                float2 f1 = unpack2(acc2[i][q * 2 + 1]);
                float4 v = make_float4(f0.x, f0.y, f1.x, f1.y);
                *(float4*)&op[tx * 4 + 64 * q] = v;
            }
        }
    }
}

// ---------------------------------------------------------------------------
extern "C" void kernel_launch(void* const* d_in, const int* in_sizes, int n_in,
                              void* d_out, int out_size) {
    const float* X  = (const float*)d_in[0];
    const float* H  = (const float*)d_in[1];
    const float* W1 = (const float*)d_in[2];
    const float* W2 = (const float*)d_in[3];
    float* out = (float*)d_out;

    z_kernel<<<dim3(3, Bn), 256>>>(X, W2);
    y_kernel<<<dim3(44, Bn), 192>>>(W1);
    l_kernel<<<dim3(NUT, 3, Bn), 256>>>(H);
    combine_kernel<<<(Bn * CNn + 255) / 256, 256>>>();
    c_kernel<<<dim3(6, Bn), 256>>>(H, out);
}

// round 12
// speedup vs baseline: 2.2653x; 1.1011x over previous
#include <cuda_runtime.h>
#include <math.h>
#include <stdint.h>

#define Bn  64
#define Tn  1380
#define XDn 96
#define HDn 192
#define CNn 345
#define NUT 11            // ceil(1380/128) u-tiles

// SCALE = 1/sqrt(96*192)
#define SCALEF 0.007365695637359841f
#define NEGBIG -1e30f

typedef unsigned long long u64;

// ---- packed fp32x2 helpers (exact fp32 per lane) ---------------------------
__device__ __forceinline__ u64 pack2(float x, float y) {
    u64 r; asm("mov.b64 %0, {%1, %2};" : "=l"(r) : "f"(x), "f"(y)); return r;
}
__device__ __forceinline__ float2 unpack2(u64 v) {
    float lo, hi; asm("mov.b64 {%0, %1}, %2;" : "=f"(lo), "=f"(hi) : "l"(v));
    return make_float2(lo, hi);
}
__device__ __forceinline__ void fma2(u64& d, u64 a, u64 b) {
    asm("fma.rn.f32x2 %0, %1, %2, %0;" : "+l"(d) : "l"(a), "l"(b));
}

// ---- split-tf32 helpers ----------------------------------------------------
#define TFMASK 0xFFFFE000u
__device__ __forceinline__ uint32_t hi_tf(float x) {
    return __float_as_uint(x) & TFMASK;
}
__device__ __forceinline__ uint32_t lo_tf(float x) {
    float h = __uint_as_float(__float_as_uint(x) & TFMASK);
    return __float_as_uint(x - h) & TFMASK;
}
// D += A * B  (m16n8k8 tf32)
__device__ __forceinline__ void mma8(float* d, const uint32_t* a,
                                     const uint32_t* b) {
    asm volatile(
        "mma.sync.aligned.m16n8k8.row.col.f32.tf32.tf32.f32 "
        "{%0,%1,%2,%3}, {%4,%5,%6,%7}, {%8,%9}, {%0,%1,%2,%3};"
        : "+f"(d[0]), "+f"(d[1]), "+f"(d[2]), "+f"(d[3])
        : "r"(a[0]), "r"(a[1]), "r"(a[2]), "r"(a[3]), "r"(b[0]), "r"(b[1]));
}

// Scratch (allocation-free rule: __device__ globals)
__device__ float g_Z[(size_t)Bn * CNn * XDn];
__device__ float g_Y[(size_t)Bn * CNn * HDn];
__device__ float g_L[(size_t)Bn * CNn * Tn];   // holds Pu = exp(L - m_tile)
__device__ float g_pm[(size_t)Bn * CNn * NUT];
__device__ float g_ps[(size_t)Bn * CNn * NUT];
__device__ float g_mx[Bn * CNn];
__device__ float g_inv[Bn * CNn];

// guarded float4 row load (Tn tail)
__device__ __forceinline__ float4 ld4g(const float* row, int t, bool ok) {
    float4 v = make_float4(0.f, 0.f, 0.f, 0.f);
    if (ok) {
        if (t + 3 < Tn) v = *(const float4*)(row + t);
        else {
            if (t     < Tn) v.x = row[t];
            if (t + 1 < Tn) v.y = row[t + 1];
            if (t + 2 < Tn) v.z = row[t + 2];
            if (t + 3 < Tn) v.w = row[t + 3];
        }
    }
    return v;
}

// ---------------------------------------------------------------------------
// Z[b,c,x] = sum_t W2[c,t] * X[b,t,x]   (unchanged from R8)
// ---------------------------------------------------------------------------
__global__ __launch_bounds__(256) void z_kernel(const float* __restrict__ X,
                                                const float* __restrict__ W2) {
    int b  = blockIdx.y;
    int c0 = blockIdx.x * 128;
    __shared__ float As[16][132];
    __shared__ float Bs[16][100];
    int tid = threadIdx.x, tx = tid & 15, ty = tid >> 4;
    const float* Xb = X + (size_t)b * Tn * XDn;

    int rf = tid >> 1;
    int k4 = (tid & 1) * 8;
    int ca = c0 + rf;
    bool cav = ca < CNn;
    const float* W2r = W2 + (size_t)(cav ? ca : 0) * Tn;

    int brow[3], bx2[3];
    #pragma unroll
    for (int i = 0; i < 3; i++) {
        int l = tid + 256 * i;
        brow[i] = l / 48;
        bx2[i]  = (l % 48) * 2;
    }

    float4 wa0 = ld4g(W2r, k4,     cav);
    float4 wa1 = ld4g(W2r, k4 + 4, cav);
    float2 xb[3];
    #pragma unroll
    for (int i = 0; i < 3; i++) {
        int t = brow[i];
        xb[i] = (t < Tn) ? *(const float2*)(Xb + (size_t)t * XDn + bx2[i])
                         : make_float2(0.f, 0.f);
    }

    u64 acc2[8][3] = {};

    for (int k0 = 0; k0 < Tn; k0 += 16) {
        As[k4 + 0][rf] = wa0.x; As[k4 + 1][rf] = wa0.y;
        As[k4 + 2][rf] = wa0.z; As[k4 + 3][rf] = wa0.w;
        As[k4 + 4][rf] = wa1.x; As[k4 + 5][rf] = wa1.y;
        As[k4 + 6][rf] = wa1.z; As[k4 + 7][rf] = wa1.w;
        #pragma unroll
        for (int i = 0; i < 3; i++)
            *(float2*)&Bs[brow[i]][bx2[i]] = xb[i];
        __syncthreads();

        if (k0 + 16 < Tn) {
            wa0 = ld4g(W2r, k0 + 16 + k4,     cav);
            wa1 = ld4g(W2r, k0 + 16 + k4 + 4, cav);
            #pragma unroll
            for (int i = 0; i < 3; i++) {
                int t = k0 + 16 + brow[i];
                xb[i] = (t < Tn) ? *(const float2*)(Xb + (size_t)t * XDn + bx2[i])
                                 : make_float2(0.f, 0.f);
            }
        }

        #pragma unroll
        for (int k = 0; k < 16; k++) {
            float4 a0 = *(const float4*)&As[k][ty * 4];
            float4 a1 = *(const float4*)&As[k][64 + ty * 4];
            u64 bp[3];
            bp[0] = *(const u64*)&Bs[k][tx * 6 + 0];
            bp[1] = *(const u64*)&Bs[k][tx * 6 + 2];
            bp[2] = *(const u64*)&Bs[k][tx * 6 + 4];
            float av[8] = {a0.x, a0.y, a0.z, a0.w, a1.x, a1.y, a1.z, a1.w};
            u64 ap[8];
            #pragma unroll
            for (int i = 0; i < 8; i++) ap[i] = pack2(av[i], av[i]);
            #pragma unroll
            for (int i = 0; i < 8; i++)
                #pragma unroll
                for (int j = 0; j < 3; j++)
                    fma2(acc2[i][j], ap[i], bp[j]);
        }
        __syncthreads();
    }

    float* Zb = g_Z + (size_t)b * CNn * XDn;
    #pragma unroll
    for (int i = 0; i < 8; i++) {
        int c = c0 + ((i < 4) ? (ty * 4 + i) : (64 + ty * 4 + i - 4));
        if (c < CNn) {
            float* zp = Zb + (size_t)c * XDn + tx * 6;
            #pragma unroll
            for (int j = 0; j < 3; j++) {
                float2 f = unpack2(acc2[i][j]);
                *(float2*)(zp + 2 * j) = f;
            }
        }
    }
}

// ---------------------------------------------------------------------------
// Y[b,c,h] = SCALE * sum_x Z[b,c,x] * W1[x,h]   (unchanged)
// ---------------------------------------------------------------------------
__global__ __launch_bounds__(192) void y_kernel(const float* __restrict__ W1) {
    int b  = blockIdx.y;
    int c0 = blockIdx.x * 8;
    __shared__ float Zs[8][96];
    const float* Zb = g_Z + (size_t)b * CNn * XDn;
    for (int l = threadIdx.x; l < 8 * 96; l += 192) {
        int r = l / 96, x = l % 96;
        int c = c0 + r;
        Zs[r][x] = (c < CNn) ? Zb[(size_t)c * XDn + x] : 0.f;
    }
    __syncthreads();
    int h = threadIdx.x;
    float acc[8] = {};
    for (int x = 0; x < 96; x++) {
        float w = W1[(size_t)x * HDn + h];
        #pragma unroll
        for (int r = 0; r < 8; r++) acc[r] = fmaf(Zs[r][x], w, acc[r]);
    }
    float* Yb = g_Y + (size_t)b * CNn * HDn;
    #pragma unroll
    for (int r = 0; r < 8; r++) {
        int c = c0 + r;
        if (c < CNn) Yb[(size_t)c * HDn + h] = acc[r] * SCALEF;
    }
}

// ===========================================================================
// l_mma_kernel: L = Y @ H^T via mma.sync m16n8k8 tf32, split-3 (exact~2^-22).
// Block 128c x 128u, 8 warps (4 c-dir x 2 u-dir), warp tile 32x64 = 2x8 atoms.
// Full K=192 in smem ([row][196] pad, conflict-free). Epilogue: per-tile
// (max, sumexp) partials + stores Pu = exp(L - m_tile) into g_L.
// ===========================================================================
#define LPAD 196
#define LSM_BYTES (2 * 128 * LPAD * 4)   // 200704

__global__ __launch_bounds__(256) void l_mma_kernel(const float* __restrict__ H) {
    extern __shared__ float sm[];
    float* Ys = sm;                  // [128][196]
    float* Hs = sm + 128 * LPAD;     // [128][196]
    int b  = blockIdx.z;
    int c0 = blockIdx.y * 128;
    int u0 = blockIdx.x * 128;
    int ut = blockIdx.x;
    int tid = threadIdx.x;
    int wid = tid >> 5, lane = tid & 31, gid = lane >> 2, tg = lane & 3;
    int wm = wid & 3, wn = wid >> 2;     // c: wm*32, u: wn*64

    const float* Yb = g_Y + (size_t)b * CNn * HDn;
    const float* Hb = H + (size_t)b * Tn * HDn;
    const float4 z4 = make_float4(0.f, 0.f, 0.f, 0.f);

    #pragma unroll
    for (int i = 0; i < 24; i++) {
        int idx = tid + 256 * i;
        int r = idx / 48, kk = (idx % 48) * 4;
        int c = c0 + r;
        float4 v = (c < CNn) ? *(const float4*)(Yb + (size_t)c * HDn + kk) : z4;
        *(float4*)&Ys[r * LPAD + kk] = v;
        int u = u0 + r;
        float4 w = (u < Tn) ? *(const float4*)(Hb + (size_t)u * HDn + kk) : z4;
        *(float4*)&Hs[r * LPAD + kk] = w;
    }
    __syncthreads();

    float d[2][8][4];
    #pragma unroll
    for (int i = 0; i < 2; i++)
        #pragma unroll
        for (int j = 0; j < 8; j++)
            #pragma unroll
            for (int q = 0; q < 4; q++) d[i][j][q] = 0.f;

    int arow = (wm * 32 + gid) * LPAD;
    int brow = (wn * 64 + gid) * LPAD;

    #pragma unroll 1
    for (int kk = 0; kk < 24; kk++) {
        int k = kk * 8 + tg;
        uint32_t ahi[2][4], alo[2][4], bhi[8][2], blo[8][2];
        #pragma unroll
        for (int i = 0; i < 2; i++) {
            const float* p = &Ys[arow + i * 16 * LPAD + k];
            float f0 = p[0], f1 = p[8 * LPAD], f2 = p[4], f3 = p[8 * LPAD + 4];
            ahi[i][0] = hi_tf(f0); alo[i][0] = lo_tf(f0);
            ahi[i][1] = hi_tf(f1); alo[i][1] = lo_tf(f1);
            ahi[i][2] = hi_tf(f2); alo[i][2] = lo_tf(f2);
            ahi[i][3] = hi_tf(f3); alo[i][3] = lo_tf(f3);
        }
        #pragma unroll
        for (int j = 0; j < 8; j++) {
            const float* p = &Hs[brow + j * 8 * LPAD + k];
            float g0 = p[0], g1 = p[4];
            bhi[j][0] = hi_tf(g0); blo[j][0] = lo_tf(g0);
            bhi[j][1] = hi_tf(g1); blo[j][1] = lo_tf(g1);
        }
        #pragma unroll
        for (int i = 0; i < 2; i++)
            #pragma unroll
            for (int j = 0; j < 8; j++) {
                mma8(d[i][j], ahi[i], bhi[j]);
                mma8(d[i][j], ahi[i], blo[j]);
                mma8(d[i][j], alo[i], bhi[j]);
            }
    }

    // ---- epilogue: per-row tile max/sumexp; store Pu = exp(d - m) ----
    __syncthreads();                 // smem reuse
    float* redm = sm;                // [2][128]
    float* reds = sm + 256;          // [2][128]
    int ubase = u0 + wn * 64;

    float mloc[4] = {NEGBIG, NEGBIG, NEGBIG, NEGBIG};
    #pragma unroll
    for (int i = 0; i < 2; i++)
        #pragma unroll
        for (int j = 0; j < 8; j++)
            #pragma unroll
            for (int p = 0; p < 2; p++)
                #pragma unroll
                for (int q = 0; q < 2; q++) {
                    int u = ubase + j * 8 + tg * 2 + q;
                    if (u < Tn)
                        mloc[i * 2 + p] = fmaxf(mloc[i * 2 + p], d[i][j][p * 2 + q]);
                }
    #pragma unroll
    for (int ri = 0; ri < 4; ri++) {
        mloc[ri] = fmaxf(mloc[ri], __shfl_xor_sync(0xffffffffu, mloc[ri], 1));
        mloc[ri] = fmaxf(mloc[ri], __shfl_xor_sync(0xffffffffu, mloc[ri], 2));
    }
    if (tg == 0) {
        #pragma unroll
        for (int ri = 0; ri < 4; ri++) {
            int rl = wm * 32 + (ri >> 1) * 16 + gid + (ri & 1) * 8;
            redm[wn * 128 + rl] = mloc[ri];
        }
    }
    __syncthreads();

    float* Lb = g_L + (size_t)b * CNn * Tn;
    float ssum[4] = {0.f, 0.f, 0.f, 0.f};
    #pragma unroll
    for (int i = 0; i < 2; i++)
        #pragma unroll
        for (int p = 0; p < 2; p++) {
            int ri = i * 2 + p;
            int rl = wm * 32 + i * 16 + gid + p * 8;
            int c  = c0 + rl;
            float m = fmaxf(redm[rl], redm[128 + rl]);
            #pragma unroll
            for (int j = 0; j < 8; j++) {
                int u = ubase + j * 8 + tg * 2;
                float e0 = __expf(d[i][j][p * 2 + 0] - m);
                float e1 = __expf(d[i][j][p * 2 + 1] - m);
                if (u < Tn) {
                    ssum[ri] += e0 + e1;
                    if (c < CNn)
                        *(float2*)&Lb[(size_t)c * Tn + u] = make_float2(e0, e1);
                }
            }
        }
    #pragma unroll
    for (int ri = 0; ri < 4; ri++) {
        ssum[ri] += __shfl_xor_sync(0xffffffffu, ssum[ri], 1);
        ssum[ri] += __shfl_xor_sync(0xffffffffu, ssum[ri], 2);
    }
    if (tg == 0) {
        #pragma unroll
        for (int ri = 0; ri < 4; ri++) {
            int rl = wm * 32 + (ri >> 1) * 16 + gid + (ri & 1) * 8;
            reds[wn * 128 + rl] = ssum[ri];
        }
    }
    __syncthreads();
    if (tid < 128) {
        int c = c0 + tid;
        if (c < CNn) {
            size_t ridx = ((size_t)b * CNn + c) * NUT + ut;
            g_pm[ridx] = fmaxf(redm[tid], redm[128 + tid]);
            g_ps[ridx] = reds[tid] + reds[128 + tid];
        }
    }
}

// ---------------------------------------------------------------------------
// Combine per-tile softmax partials (unchanged semantics)
// ---------------------------------------------------------------------------
__global__ __launch_bounds__(256) void combine_kernel() {
    int idx = blockIdx.x * 256 + threadIdx.x;
    if (idx >= Bn * CNn) return;
    const float* pm = g_pm + (size_t)idx * NUT;
    const float* ps = g_ps + (size_t)idx * NUT;
    float m = NEGBIG;
    #pragma unroll
    for (int t = 0; t < NUT; t++) m = fmaxf(m, pm[t]);
    float s = 0.f;
    #pragma unroll
    for (int t = 0; t < NUT; t++) s += ps[t] * __expf(pm[t] - m);
    g_mx[idx]  = m;
    g_inv[idx] = 1.0f / s;
}

// ===========================================================================
// c_mma_kernel: C = P @ H via mma.sync tf32 split-3.
// P = Pu * f, with f[row][ut] = exp(m_t - M) * inv  (704-entry table/block).
// Block 64c x 192h, BK=32 u; 8 warps (2 c-dir x 4 h-dir), warp 32x48 = 2x6.
// ===========================================================================
#define CPADA 36
#define CPADB 200

__global__ __launch_bounds__(256) void c_mma_kernel(const float* __restrict__ H,
                                                    float* __restrict__ out) {
    __shared__ float Ps[64 * CPADA];       // 9216 B
    __shared__ float Hs[32 * CPADB];       // 25600 B
    __shared__ float f_s[64 * NUT];        // 2816 B
    int b  = blockIdx.y;
    int c0 = blockIdx.x * 64;
    int tid = threadIdx.x;
    int wid = tid >> 5, lane = tid & 31, gid = lane >> 2, tg = lane & 3;
    int wm = wid & 1, wn = wid >> 1;       // c: wm*32, h: wn*48

    // correction-factor table
    for (int idx = tid; idx < 64 * NUT; idx += 256) {
        int row = idx / NUT, t = idx - row * NUT;
        int c = c0 + row;
        float f = 0.f;
        if (c < CNn) {
            int rc = b * CNn + c;
            f = __expf(g_pm[(size_t)rc * NUT + t] - g_mx[rc]) * g_inv[rc];
        }
        f_s[idx] = f;
    }
    __syncthreads();

    const float* Lb = g_L + (size_t)b * CNn * Tn;
    const float* Hb = H + (size_t)b * Tn * HDn;
    const float4 z4 = make_float4(0.f, 0.f, 0.f, 0.f);

    float d[2][6][4];
    #pragma unroll
    for (int i = 0; i < 2; i++)
        #pragma unroll
        for (int j = 0; j < 6; j++)
            #pragma unroll
            for (int q = 0; q < 4; q++) d[i][j][q] = 0.f;

    int arow = (wm * 32 + gid) * CPADA;
    int nb   = wn * 48 + gid;

    #pragma unroll 1
    for (int ch = 0; ch < 44; ch++) {
        int u0c = ch * 32;
        int utt = ch >> 2;
        // fill P tile (64 x 32), scaled
        #pragma unroll
        for (int i = 0; i < 2; i++) {
            int idx = tid + 256 * i;         // float4 index, 0..511
            int r = idx >> 3, uu = (idx & 7) * 4;
            int c = c0 + r;
            int u = u0c + uu;
            float4 v = (c < CNn && u < Tn)
                       ? *(const float4*)(Lb + (size_t)c * Tn + u) : z4;
            float f = f_s[r * NUT + utt];
            v.x *= f; v.y *= f; v.z *= f; v.w *= f;
            *(float4*)&Ps[r * CPADA + uu] = v;
        }
        // fill H tile (32 x 192)
        #pragma unroll
        for (int i = 0; i < 6; i++) {
            int idx = tid + 256 * i;         // 0..1535
            int r = idx / 48, hh = (idx % 48) * 4;
            int u = u0c + r;
            float4 w = (u < Tn) ? *(const float4*)(Hb + (size_t)u * HDn + hh) : z4;
            *(float4*)&Hs[r * CPADB + hh] = w;
        }
        __syncthreads();

        #pragma unroll
        for (int kk = 0; kk < 4; kk++) {
            int k = kk * 8 + tg;
            uint32_t ahi[2][4], alo[2][4], bhi[6][2], blo[6][2];
            #pragma unroll
            for (int i = 0; i < 2; i++) {
                const float* p = &Ps[arow + i * 16 * CPADA + k];
                float f0 = p[0], f1 = p[8 * CPADA], f2 = p[4], f3 = p[8 * CPADA + 4];
                ahi[i][0] = hi_tf(f0); alo[i][0] = lo_tf(f0);
                ahi[i][1] = hi_tf(f1); alo[i][1] = lo_tf(f1);
                ahi[i][2] = hi_tf(f2); alo[i][2] = lo_tf(f2);
                ahi[i][3] = hi_tf(f3); alo[i][3] = lo_tf(f3);
            }
            #pragma unroll
            for (int j = 0; j < 6; j++) {
                const float* p = &Hs[k * CPADB + nb + j * 8];
                float g0 = p[0], g1 = p[4 * CPADB];
                bhi[j][0] = hi_tf(g0); blo[j][0] = lo_tf(g0);
                bhi[j][1] = hi_tf(g1); blo[j][1] = lo_tf(g1);
            }
            #pragma unroll
            for (int i = 0; i < 2; i++)
                #pragma unroll
                for (int j = 0; j < 6; j++) {
                    mma8(d[i][j], ahi[i], bhi[j]);
                    mma8(d[i][j], ahi[i], blo[j]);
                    mma8(d[i][j], alo[i], bhi[j]);
                }
        }
        __syncthreads();
    }

    // epilogue: direct store (P already normalized)
    #pragma unroll
    for (int i = 0; i < 2; i++)
        #pragma unroll
        for (int p = 0; p < 2; p++) {
            int c = c0 + wm * 32 + i * 16 + gid + p * 8;
            if (c < CNn) {
                float* op = out + ((size_t)b * CNn + c) * HDn;
                #pragma unroll
                for (int j = 0; j < 6; j++) {
                    int h = wn * 48 + j * 8 + tg * 2;
                    *(float2*)&op[h] = make_float2(d[i][j][p * 2 + 0],
                                                   d[i][j][p * 2 + 1]);
                }
            }
        }
}

// ---------------------------------------------------------------------------
extern "C" void kernel_launch(void* const* d_in, const int* in_sizes, int n_in,
                              void* d_out, int out_size) {
    const float* X  = (const float*)d_in[0];
    const float* H  = (const float*)d_in[1];
    const float* W1 = (const float*)d_in[2];
    const float* W2 = (const float*)d_in[3];
    float* out = (float*)d_out;

    cudaFuncSetAttribute(l_mma_kernel,
                         cudaFuncAttributeMaxDynamicSharedMemorySize, LSM_BYTES);

    z_kernel<<<dim3(3, Bn), 256>>>(X, W2);
    y_kernel<<<dim3(44, Bn), 192>>>(W1);
    l_mma_kernel<<<dim3(NUT, 3, Bn), 256, LSM_BYTES>>>(H);
    combine_kernel<<<(Bn * CNn + 255) / 256, 256>>>();
    c_mma_kernel<<<dim3(6, Bn), 256>>>(H, out);
}